// round 4
// baseline (speedup 1.0000x reference)
#include <cuda_runtime.h>
#include <cstddef>

// Problem constants (fixed-shape benchmark)
#define VV   2048
#define NN   16
#define DI   32
#define DO   64
#define NH   8
#define NT   1152          // tasks = H*12*12
#define CID  192           // DI*6
#define EDIM 2496          // 32*13*6
#define MROW 29952         // 12*EDIM
#define KA_ELEMS (DO*VV*6)     // 786432
#define FM_ELEMS (DI*VV*6)     // 393216

typedef unsigned long long u64;

// ---------------- f32x2 packed helpers ----------------
__device__ __forceinline__ u64 bc2(float x) {
    u64 r; asm("mov.b64 %0,{%1,%1};" : "=l"(r) : "f"(x)); return r;
}
__device__ __forceinline__ u64 pk2(float x, float y) {
    u64 r; asm("mov.b64 %0,{%1,%2};" : "=l"(r) : "f"(x), "f"(y)); return r;
}
__device__ __forceinline__ void up2(float& x, float& y, u64 v) {
    asm("mov.b64 {%0,%1},%2;" : "=f"(x), "=f"(y) : "l"(v));
}
__device__ __forceinline__ void fma2(u64& d, u64 a, u64 b) {
    asm("fma.rn.f32x2 %0,%1,%2,%0;" : "+l"(d) : "l"(a), "l"(b));
}

// ---------------- constant tables ----------------
__constant__ int cINV[12][6] = {
    {0,1,2,3,4,5},{0,5,4,3,2,1},{4,3,0,5,2,1},{1,2,4,3,5,0},
    {3,5,2,0,4,1},{1,4,3,5,0,2},{4,0,3,1,2,5},{1,0,2,4,3,5},
    {4,1,2,5,0,3},{3,1,4,0,2,5},{2,1,4,5,3,0},{4,5,0,3,1,2}};
__constant__ int cROLL[5][6] = {
    {0,1,2,3,4,5},{0,2,3,4,5,1},{0,3,4,5,1,2},{0,4,5,1,2,3},{0,5,1,2,3,4}};
__constant__ int cC2V[6][2] = {{0,1},{6,7},{2,11},{4,9},{5,8},{3,10}};
#define PHI 1.6180339887498949f
__constant__ float cVSU[12][3] = {
    {0.f,1.f,PHI},{0.f,1.f,-PHI},{0.f,-1.f,PHI},{0.f,-1.f,-PHI},
    {1.f,PHI,0.f},{1.f,-PHI,0.f},{-1.f,PHI,0.f},{-1.f,-PHI,0.f},
    {PHI,0.f,1.f},{PHI,0.f,-1.f},{-PHI,0.f,1.f},{-PHI,0.f,-1.f}};

// ---------------- device scratch ----------------
__device__ float g_Wdr[CID * NT];                 // [ci][task], task=h*144+k*12+r, includes 0.5 scale
__device__ float g_Wg[12 * DO * EDIM];            // [r][d][e], e=(c*13+k)*6+i
__device__ float g_M[(size_t)VV * MROW];          // [p][r][e]
__device__ float g_feat[12 * DO * VV];            // [r][d][p]

// ---------------- symmetry expansion ----------------
__device__ __forceinline__ float w13v(const float* Wp, int k, int j) {
    if (k == 0)  return (j == 0) ? Wp[0] : Wp[1];
    if (k == 1)  return (j == 0) ? Wp[2] : Wp[3];
    if (k == 12) return (j == 0) ? Wp[4] : Wp[5];
    if (k < 7)   return Wp[6  + cROLL[k - 2][j]];
    return               Wp[12 + cROLL[k - 7][j]];
}

__global__ void prepWdr(const float* __restrict__ Wdir) {
    int idx = blockIdx.x * blockDim.x + threadIdx.x;
    if (idx >= CID * NT) return;
    int t = idx % NT, ci = idx / NT;
    int c = ci / 6, i = ci % 6;
    int h = t / 144, k = (t / 12) % 12, r = t % 12;
    const float* Wp = Wdir + (h * 32 + c) * 18;
    g_Wdr[idx] = 0.5f * w13v(Wp, k, cINV[r][i]);   // fold 1/sqrt(dph)=0.5
}

__global__ void prepWg(const float* __restrict__ W) {
    int idx = blockIdx.x * blockDim.x + threadIdx.x;
    if (idx >= 12 * DO * EDIM) return;
    int e = idx % EDIM;
    int d = (idx / EDIM) % DO;
    int r = idx / (EDIM * DO);
    int c = e / 78, rem = e % 78, k = rem / 6, i = rem % 6;
    const float* Wp = W + (d * 32 + c) * 18;
    g_Wg[idx] = w13v(Wp, k, cINV[r][i]);
}

// ---------------- kernel A: 2 vertices/block, packed f32x2 ----------------
__global__ __launch_bounds__(192) void kernA(const int* __restrict__ nbr_idx,
                                             const float* __restrict__ verts,
                                             const float* __restrict__ fm,
                                             const float* __restrict__ wdim) {
    const int p0 = blockIdx.x * 2;
    const int tid = threadIdx.x;
    __shared__ __align__(16) float s_cross[2][CID * 16];   // [v][ci][n]
    __shared__ __align__(16) float s_wdim[33 * 32];
    __shared__ float s_de[2][96];
    __shared__ int s_nbr[2][16];

    for (int t = tid; t < 33 * 32; t += 192) s_wdim[t] = wdim[t];

    if (tid < 32) {
        int v = tid >> 4, n = tid & 15;
        int p = p0 + v;
        int nb = nbr_idx[p * NN + n];
        s_nbr[v][n] = nb;
        float px = verts[p * 3], py = verts[p * 3 + 1], pz = verts[p * 3 + 2];
        float dx = verts[nb * 3] - px;
        float dy = verts[nb * 3 + 1] - py;
        float dz = verts[nb * 3 + 2] - pz;
        float nrm = sqrtf(dx * dx + dy * dy + dz * dz);
        float inv = 1.0f / fmaxf(nrm, 1e-12f);
        dx *= inv; dy *= inv; dz *= inv;
        const float invn = rsqrtf(2.0f + PHI);
        float d0[12];
#pragma unroll
        for (int q = 0; q < 12; q++)
            d0[q] = (cVSU[q][0] * dx + cVSU[q][1] * dy + cVSU[q][2] * dz) * invn;
#pragma unroll
        for (int col = 0; col < 6; col++)
            s_de[v][n * 6 + col] = fmaxf(d0[cC2V[col][0]], d0[cC2V[col][1]]);
    }
    __syncthreads();

    // cross: 192 threads = 2v * 96 (n,i) tasks
    {
        int v = tid / 96, t0 = tid % 96;
        int n = t0 / 6, i = t0 % 6;
        int nb = s_nbr[v][n];
        u64 acc[16];
#pragma unroll
        for (int q = 0; q < 16; q++) acc[q] = 0ull;
        for (int c = 0; c < 33; c++) {
            float x = (c < 32) ? fm[((size_t)c * VV + nb) * 6 + i] : s_de[v][n * 6 + i];
            u64 xb = bc2(x);
            const u64* wd2 = (const u64*)&s_wdim[c * 32];
#pragma unroll
            for (int q = 0; q < 16; q++) fma2(acc[q], wd2[q], xb);
        }
#pragma unroll
        for (int q = 0; q < 16; q++) {
            float o0, o1; up2(o0, o1, acc[q]);
            s_cross[v][((2 * q)     * 6 + i) * 16 + n] = o0;
            s_cross[v][((2 * q + 1) * 6 + i) * 16 + n] = o1;
        }
    }

    // center (k=12) slices of M: 2v * 192 ci
    for (int v = 0; v < 2; v++) {
        int c = tid / 6, i = tid % 6;
        float val = fm[((size_t)c * VV + p0 + v) * 6 + i];
        size_t base = (size_t)(p0 + v) * MROW + (size_t)(c * 13 + 12) * 6 + i;
#pragma unroll
        for (int r = 0; r < 12; r++) g_M[base + (size_t)r * EDIM] = val;
    }
    __syncthreads();

    const u64* cs2a = (const u64*)s_cross[0];
    const u64* cs2b = (const u64*)s_cross[1];

    // act: each thread handles 1 task for both vertices; 6 iterations cover 1152 tasks
    for (int it = 0; it < 6; it++) {
        int t = tid + 192 * it;
        int h = t / 144;
        int k = (t / 12) % 12;
        int r = t % 12;
        u64 a0[8], a1[8];
#pragma unroll
        for (int q = 0; q < 8; q++) { a0[q] = 0ull; a1[q] = 0ull; }
        const float* wp = g_Wdr + t;
#pragma unroll 4
        for (int ci = 0; ci < CID; ci++) {
            float w = wp[(size_t)ci * NT];
            u64 wb = bc2(w);
            const u64* c0 = cs2a + ci * 8;
            const u64* c1 = cs2b + ci * 8;
#pragma unroll
            for (int q = 0; q < 8; q++) {
                fma2(a0[q], wb, c0[q]);
                fma2(a1[q], wb, c1[q]);
            }
        }
#pragma unroll
        for (int v = 0; v < 2; v++) {
            const u64* ap  = v ? a1 : a0;
            const u64* cs2 = v ? cs2b : cs2a;
            float a[16];
#pragma unroll
            for (int q = 0; q < 8; q++) up2(a[2 * q], a[2 * q + 1], ap[q]);
            float m = a[0];
#pragma unroll
            for (int n = 1; n < 16; n++) m = fmaxf(m, a[n]);
            float s = 0.f;
#pragma unroll
            for (int n = 0; n < 16; n++) { a[n] = __expf(a[n] - m); s += a[n]; }
            float invs = 1.0f / s;
            u64 apk[8];
#pragma unroll
            for (int q = 0; q < 8; q++) apk[q] = pk2(a[2 * q] * invs, a[2 * q + 1] * invs);
            size_t base = (size_t)(p0 + v) * MROW + (size_t)r * EDIM;
#pragma unroll
            for (int cc = 0; cc < 4; cc++) {
                int c = h * 4 + cc;
                float mv[6];
#pragma unroll
                for (int i = 0; i < 6; i++) {
                    const u64* cp = cs2 + (c * 6 + i) * 8;
                    u64 s2 = 0ull;
#pragma unroll
                    for (int q = 0; q < 8; q++) fma2(s2, apk[q], cp[q]);
                    float x, y; up2(x, y, s2);
                    mv[i] = x + y;
                }
                float2* dst2 = (float2*)&g_M[base + (size_t)(c * 13 + k) * 6];
                dst2[0] = make_float2(mv[0], mv[1]);
                dst2[1] = make_float2(mv[2], mv[3]);
                dst2[2] = make_float2(mv[4], mv[5]);
            }
        }
    }
}

// ---------------- kernel B: feat[r] (64 x 2048) = Wg[r] (64 x 2496) @ M (2496 x 2048) ----------------
// 128 threads, tile 64d x 64p, 4d x 8p per thread, packed f32x2
__global__ __launch_bounds__(128) void kernB() {
    const int r  = blockIdx.y;
    const int p1 = blockIdx.x * 64;
    const int tid = threadIdx.x;
    __shared__ __align__(16) float Wt[2][16][64];
    __shared__ __align__(16) float Mt[2][16][64];

    const int ld = tid & 63, lj0 = tid >> 6;         // loader: row ld, chunks lj0, lj0+2
    const float* wbase = g_Wg + ((size_t)r * DO + ld) * EDIM;
    const float* mbase = g_M + (size_t)(p1 + ld) * MROW + (size_t)r * EDIM;

    const int px = tid & 7, dx = tid >> 3;           // compute: 4d x 8p
    const int d0 = dx * 4, pl = px * 8;

    u64 acc[4][4];
#pragma unroll
    for (int a = 0; a < 4; a++)
#pragma unroll
        for (int b = 0; b < 4; b++) acc[a][b] = 0ull;

    // prologue: load step 0
#pragma unroll
    for (int j = 0; j < 2; j++) {
        int lj = lj0 + 2 * j;
        float4 wv = *(const float4*)(wbase + 4 * lj);
        float4 mv = *(const float4*)(mbase + 4 * lj);
        Wt[0][4 * lj + 0][ld] = wv.x; Wt[0][4 * lj + 1][ld] = wv.y;
        Wt[0][4 * lj + 2][ld] = wv.z; Wt[0][4 * lj + 3][ld] = wv.w;
        Mt[0][4 * lj + 0][ld] = mv.x; Mt[0][4 * lj + 1][ld] = mv.y;
        Mt[0][4 * lj + 2][ld] = mv.z; Mt[0][4 * lj + 3][ld] = mv.w;
    }
    __syncthreads();

    int buf = 0;
    const int NSTEP = EDIM / 16;   // 156
    for (int s = 0; s < NSTEP; s++) {
        float4 wpre[2], mpre[2];
        if (s + 1 < NSTEP) {
            int e0 = (s + 1) * 16;
#pragma unroll
            for (int j = 0; j < 2; j++) {
                int lj = lj0 + 2 * j;
                wpre[j] = *(const float4*)(wbase + e0 + 4 * lj);
                mpre[j] = *(const float4*)(mbase + e0 + 4 * lj);
            }
        }
#pragma unroll
        for (int e = 0; e < 16; e++) {
            float4 wv = *(const float4*)&Wt[buf][e][d0];
            const u64* mp = (const u64*)&Mt[buf][e][pl];
            u64 m0 = mp[0], m1 = mp[1], m2 = mp[2], m3 = mp[3];
            u64 w0 = bc2(wv.x), w1 = bc2(wv.y), w2 = bc2(wv.z), w3 = bc2(wv.w);
            fma2(acc[0][0], w0, m0); fma2(acc[0][1], w0, m1); fma2(acc[0][2], w0, m2); fma2(acc[0][3], w0, m3);
            fma2(acc[1][0], w1, m0); fma2(acc[1][1], w1, m1); fma2(acc[1][2], w1, m2); fma2(acc[1][3], w1, m3);
            fma2(acc[2][0], w2, m0); fma2(acc[2][1], w2, m1); fma2(acc[2][2], w2, m2); fma2(acc[2][3], w2, m3);
            fma2(acc[3][0], w3, m0); fma2(acc[3][1], w3, m1); fma2(acc[3][2], w3, m2); fma2(acc[3][3], w3, m3);
        }
        __syncthreads();
        if (s + 1 < NSTEP) {
            int nb = buf ^ 1;
#pragma unroll
            for (int j = 0; j < 2; j++) {
                int lj = lj0 + 2 * j;
                Wt[nb][4 * lj + 0][ld] = wpre[j].x; Wt[nb][4 * lj + 1][ld] = wpre[j].y;
                Wt[nb][4 * lj + 2][ld] = wpre[j].z; Wt[nb][4 * lj + 3][ld] = wpre[j].w;
                Mt[nb][4 * lj + 0][ld] = mpre[j].x; Mt[nb][4 * lj + 1][ld] = mpre[j].y;
                Mt[nb][4 * lj + 2][ld] = mpre[j].z; Mt[nb][4 * lj + 3][ld] = mpre[j].w;
            }
            __syncthreads();
        }
        buf ^= 1;
    }

#pragma unroll
    for (int dy = 0; dy < 4; dy++) {
        float o[8];
#pragma unroll
        for (int q = 0; q < 4; q++) up2(o[2 * q], o[2 * q + 1], acc[dy][q]);
        float* dst = &g_feat[((size_t)r * DO + d0 + dy) * VV + p1 + pl];
        *(float4*)(dst)     = make_float4(o[0], o[1], o[2], o[3]);
        *(float4*)(dst + 4) = make_float4(o[4], o[5], o[6], o[7]);
    }
}

// ---------------- kernel C: ka = max over C2V pairs of feat ----------------
__global__ void kernC(float* __restrict__ out) {
    int idx = blockIdx.x * blockDim.x + threadIdx.x;   // over DO*VV
    if (idx >= DO * VV) return;
    int d = idx / VV, p = idx % VV;
#pragma unroll
    for (int col = 0; col < 6; col++) {
        int r0 = cC2V[col][0], r1 = cC2V[col][1];
        float v = fmaxf(g_feat[((size_t)r0 * DO + d) * VV + p],
                        g_feat[((size_t)r1 * DO + d) * VV + p]);
        out[(size_t)idx * 6 + col] = v;
    }
}

extern "C" void kernel_launch(void* const* d_in, const int* in_sizes, int n_in,
                              void* d_out, int out_size) {
    const int*   nbr   = (const int*)d_in[0];
    const float* verts = (const float*)d_in[1];
    const float* fm    = (const float*)d_in[2];
    const float* wdim  = (const float*)d_in[3];
    const float* W     = (const float*)d_in[4];
    const float* Wdir  = (const float*)d_in[5];
    float* out = (float*)d_out;

    prepWdr<<<(CID * NT + 255) / 256, 256>>>(Wdir);
    prepWg<<<(12 * DO * EDIM + 255) / 256, 256>>>(W);
    kernA<<<VV / 2, 192>>>(nbr, verts, fm, wdim);
    dim3 gb(VV / 64, 12);
    kernB<<<gb, 128>>>();
    kernC<<<(DO * VV + 255) / 256, 256>>>(out);
    if (out_size >= KA_ELEMS + FM_ELEMS) {
        cudaMemcpyAsync(out + KA_ELEMS, fm, (size_t)FM_ELEMS * sizeof(float),
                        cudaMemcpyDeviceToDevice, 0);
    }
}

// round 5
// speedup vs baseline: 1.3215x; 1.3215x over previous
#include <cuda_runtime.h>
#include <cstddef>

// Problem constants (fixed-shape benchmark)
#define VV   2048
#define NN   16
#define DI   32
#define DO   64
#define NH   8
#define NT   1152          // tasks = H*12*12
#define CID  192           // DI*6
#define EDIM 2496          // 32*13*6
#define MROW 29952         // 12*EDIM
#define KA_ELEMS (DO*VV*6)     // 786432
#define FM_ELEMS (DI*VV*6)     // 393216

typedef unsigned long long u64;
typedef unsigned int u32;

// ---------------- f32x2 packed helpers ----------------
__device__ __forceinline__ u64 bc2(float x) {
    u64 r; asm("mov.b64 %0,{%1,%1};" : "=l"(r) : "f"(x)); return r;
}
__device__ __forceinline__ u64 pk2(float x, float y) {
    u64 r; asm("mov.b64 %0,{%1,%2};" : "=l"(r) : "f"(x), "f"(y)); return r;
}
__device__ __forceinline__ void up2(float& x, float& y, u64 v) {
    asm("mov.b64 {%0,%1},%2;" : "=f"(x), "=f"(y) : "l"(v));
}
__device__ __forceinline__ void fma2(u64& d, u64 a, u64 b) {
    asm("fma.rn.f32x2 %0,%1,%2,%0;" : "+l"(d) : "l"(a), "l"(b));
}
__device__ __forceinline__ float tf32r(float x) {
    u32 r; asm("cvt.rna.tf32.f32 %0,%1;" : "=r"(r) : "f"(x));
    return __uint_as_float(r);
}
__device__ __forceinline__ void mma_tf32(float c[4], u32 a0, u32 a1, u32 a2, u32 a3,
                                         u32 b0, u32 b1) {
    asm volatile("mma.sync.aligned.m16n8k8.row.col.f32.tf32.tf32.f32 "
                 "{%0,%1,%2,%3}, {%4,%5,%6,%7}, {%8,%9}, {%0,%1,%2,%3};"
                 : "+f"(c[0]), "+f"(c[1]), "+f"(c[2]), "+f"(c[3])
                 : "r"(a0), "r"(a1), "r"(a2), "r"(a3), "r"(b0), "r"(b1));
}

// ---------------- constant tables ----------------
__constant__ int cINV[12][6] = {
    {0,1,2,3,4,5},{0,5,4,3,2,1},{4,3,0,5,2,1},{1,2,4,3,5,0},
    {3,5,2,0,4,1},{1,4,3,5,0,2},{4,0,3,1,2,5},{1,0,2,4,3,5},
    {4,1,2,5,0,3},{3,1,4,0,2,5},{2,1,4,5,3,0},{4,5,0,3,1,2}};
__constant__ int cROLL[5][6] = {
    {0,1,2,3,4,5},{0,2,3,4,5,1},{0,3,4,5,1,2},{0,4,5,1,2,3},{0,5,1,2,3,4}};
__constant__ int cC2V[6][2] = {{0,1},{6,7},{2,11},{4,9},{5,8},{3,10}};
#define PHI 1.6180339887498949f
__constant__ float cVSU[12][3] = {
    {0.f,1.f,PHI},{0.f,1.f,-PHI},{0.f,-1.f,PHI},{0.f,-1.f,-PHI},
    {1.f,PHI,0.f},{1.f,-PHI,0.f},{-1.f,PHI,0.f},{-1.f,-PHI,0.f},
    {PHI,0.f,1.f},{PHI,0.f,-1.f},{-PHI,0.f,1.f},{-PHI,0.f,-1.f}};

// ---------------- device scratch ----------------
__device__ float g_Wdr[CID * NT];                 // [ci][task]
__device__ float g_Wg[12 * DO * EDIM];            // [r][d][e] (tf32-rounded)
__device__ float g_M[(size_t)VV * MROW];          // [p][r][e]
__device__ float g_feat[12 * DO * VV];            // [r][d][p]

// ---------------- symmetry expansion ----------------
__device__ __forceinline__ float w13v(const float* Wp, int k, int j) {
    if (k == 0)  return (j == 0) ? Wp[0] : Wp[1];
    if (k == 1)  return (j == 0) ? Wp[2] : Wp[3];
    if (k == 12) return (j == 0) ? Wp[4] : Wp[5];
    if (k < 7)   return Wp[6  + cROLL[k - 2][j]];
    return               Wp[12 + cROLL[k - 7][j]];
}

__global__ void prepWdr(const float* __restrict__ Wdir) {
    int idx = blockIdx.x * blockDim.x + threadIdx.x;
    if (idx >= CID * NT) return;
    int t = idx % NT, ci = idx / NT;
    int c = ci / 6, i = ci % 6;
    int h = t / 144, k = (t / 12) % 12, r = t % 12;
    const float* Wp = Wdir + (h * 32 + c) * 18;
    g_Wdr[idx] = 0.5f * w13v(Wp, k, cINV[r][i]);
}

__global__ void prepWg(const float* __restrict__ W) {
    int idx = blockIdx.x * blockDim.x + threadIdx.x;
    if (idx >= 12 * DO * EDIM) return;
    int e = idx % EDIM;
    int d = (idx / EDIM) % DO;
    int r = idx / (EDIM * DO);
    int c = e / 78, rem = e % 78, k = rem / 6, i = rem % 6;
    const float* Wp = W + (d * 32 + c) * 18;
    g_Wg[idx] = tf32r(w13v(Wp, k, cINV[r][i]));   // pre-round for tensor-core GEMM
}

// ---------------- kernel A: 2 vertices/block, packed f32x2 (unchanged from R4) ----------------
__global__ __launch_bounds__(192) void kernA(const int* __restrict__ nbr_idx,
                                             const float* __restrict__ verts,
                                             const float* __restrict__ fm,
                                             const float* __restrict__ wdim) {
    const int p0 = blockIdx.x * 2;
    const int tid = threadIdx.x;
    __shared__ __align__(16) float s_cross[2][CID * 16];   // [v][ci][n]
    __shared__ __align__(16) float s_wdim[33 * 32];
    __shared__ float s_de[2][96];
    __shared__ int s_nbr[2][16];

    for (int t = tid; t < 33 * 32; t += 192) s_wdim[t] = wdim[t];

    if (tid < 32) {
        int v = tid >> 4, n = tid & 15;
        int p = p0 + v;
        int nb = nbr_idx[p * NN + n];
        s_nbr[v][n] = nb;
        float px = verts[p * 3], py = verts[p * 3 + 1], pz = verts[p * 3 + 2];
        float dx = verts[nb * 3] - px;
        float dy = verts[nb * 3 + 1] - py;
        float dz = verts[nb * 3 + 2] - pz;
        float nrm = sqrtf(dx * dx + dy * dy + dz * dz);
        float inv = 1.0f / fmaxf(nrm, 1e-12f);
        dx *= inv; dy *= inv; dz *= inv;
        const float invn = rsqrtf(2.0f + PHI);
        float d0[12];
#pragma unroll
        for (int q = 0; q < 12; q++)
            d0[q] = (cVSU[q][0] * dx + cVSU[q][1] * dy + cVSU[q][2] * dz) * invn;
#pragma unroll
        for (int col = 0; col < 6; col++)
            s_de[v][n * 6 + col] = fmaxf(d0[cC2V[col][0]], d0[cC2V[col][1]]);
    }
    __syncthreads();

    {
        int v = tid / 96, t0 = tid % 96;
        int n = t0 / 6, i = t0 % 6;
        int nb = s_nbr[v][n];
        u64 acc[16];
#pragma unroll
        for (int q = 0; q < 16; q++) acc[q] = 0ull;
        for (int c = 0; c < 33; c++) {
            float x = (c < 32) ? fm[((size_t)c * VV + nb) * 6 + i] : s_de[v][n * 6 + i];
            u64 xb = bc2(x);
            const u64* wd2 = (const u64*)&s_wdim[c * 32];
#pragma unroll
            for (int q = 0; q < 16; q++) fma2(acc[q], wd2[q], xb);
        }
#pragma unroll
        for (int q = 0; q < 16; q++) {
            float o0, o1; up2(o0, o1, acc[q]);
            s_cross[v][((2 * q)     * 6 + i) * 16 + n] = o0;
            s_cross[v][((2 * q + 1) * 6 + i) * 16 + n] = o1;
        }
    }

    for (int v = 0; v < 2; v++) {
        int c = tid / 6, i = tid % 6;
        float val = fm[((size_t)c * VV + p0 + v) * 6 + i];
        size_t base = (size_t)(p0 + v) * MROW + (size_t)(c * 13 + 12) * 6 + i;
#pragma unroll
        for (int r = 0; r < 12; r++) g_M[base + (size_t)r * EDIM] = val;
    }
    __syncthreads();

    const u64* cs2a = (const u64*)s_cross[0];
    const u64* cs2b = (const u64*)s_cross[1];

    for (int it = 0; it < 6; it++) {
        int t = tid + 192 * it;
        int h = t / 144;
        int k = (t / 12) % 12;
        int r = t % 12;
        u64 a0[8], a1[8];
#pragma unroll
        for (int q = 0; q < 8; q++) { a0[q] = 0ull; a1[q] = 0ull; }
        const float* wp = g_Wdr + t;
#pragma unroll 4
        for (int ci = 0; ci < CID; ci++) {
            float w = wp[(size_t)ci * NT];
            u64 wb = bc2(w);
            const u64* c0 = cs2a + ci * 8;
            const u64* c1 = cs2b + ci * 8;
#pragma unroll
            for (int q = 0; q < 8; q++) {
                fma2(a0[q], wb, c0[q]);
                fma2(a1[q], wb, c1[q]);
            }
        }
#pragma unroll
        for (int v = 0; v < 2; v++) {
            const u64* ap  = v ? a1 : a0;
            const u64* cs2 = v ? cs2b : cs2a;
            float a[16];
#pragma unroll
            for (int q = 0; q < 8; q++) up2(a[2 * q], a[2 * q + 1], ap[q]);
            float m = a[0];
#pragma unroll
            for (int n = 1; n < 16; n++) m = fmaxf(m, a[n]);
            float s = 0.f;
#pragma unroll
            for (int n = 0; n < 16; n++) { a[n] = __expf(a[n] - m); s += a[n]; }
            float invs = 1.0f / s;
            u64 apk[8];
#pragma unroll
            for (int q = 0; q < 8; q++) apk[q] = pk2(a[2 * q] * invs, a[2 * q + 1] * invs);
            size_t base = (size_t)(p0 + v) * MROW + (size_t)r * EDIM;
#pragma unroll
            for (int cc = 0; cc < 4; cc++) {
                int c = h * 4 + cc;
                float mv[6];
#pragma unroll
                for (int i = 0; i < 6; i++) {
                    const u64* cp = cs2 + (c * 6 + i) * 8;
                    u64 s2 = 0ull;
#pragma unroll
                    for (int q = 0; q < 8; q++) fma2(s2, apk[q], cp[q]);
                    float x, y; up2(x, y, s2);
                    mv[i] = x + y;
                }
                float2* dst2 = (float2*)&g_M[base + (size_t)(c * 13 + k) * 6];
                dst2[0] = make_float2(mv[0], mv[1]);
                dst2[1] = make_float2(mv[2], mv[3]);
                dst2[2] = make_float2(mv[4], mv[5]);
            }
        }
    }
}

// ---------------- kernel B (tensor cores): feat[r](64x2048) = Wg[r](64x2496) @ M_r(2496x2048) ----------------
// 256 threads = 8 warps. Tile 64d x 64p. Warp w: d-rows [ (w&3)*16 .. +16 ), p-half (w>>2)*32, 4 n-tiles of 8.
// smem: Wt[buf][64 d][20 e-pad], Mt[buf][64 p][20 e-pad]; pad 20 -> (g*20+t4)%32 is a permutation => conflict-free.
#define BPAD 20
__global__ __launch_bounds__(256) void kernB() {
    const int r  = blockIdx.y;
    const int p1 = blockIdx.x * 64;
    const int tid = threadIdx.x;
    __shared__ __align__(16) float Wt[2][64][BPAD];
    __shared__ __align__(16) float Mt[2][64][BPAD];

    // loader mapping: threads 0-127 load W, 128-255 load M; each 2 float4 (16 e) per row-half
    const int lsel  = tid >> 7;           // 0 = W, 1 = M
    const int lrow  = (tid >> 1) & 63;
    const int lhalf = tid & 1;            // e-offset 0 or 8
    const float* lsrc = lsel
        ? (g_M + ((size_t)(p1 + lrow)) * MROW + (size_t)r * EDIM + 8 * lhalf)
        : (g_Wg + ((size_t)r * DO + lrow) * EDIM + 8 * lhalf);

    const int lane = tid & 31, warp = tid >> 5;
    const int g = lane >> 2, t4 = lane & 3;
    const int d0 = (warp & 3) * 16;
    const int ph = (warp >> 2) * 32;      // p-half offset

    float c[4][4];
#pragma unroll
    for (int nt = 0; nt < 4; nt++)
#pragma unroll
        for (int q = 0; q < 4; q++) c[nt][q] = 0.f;

    // prologue: stage 0
    {
        float4 v0 = *(const float4*)(lsrc);
        float4 v1 = *(const float4*)(lsrc + 4);
        float* dst = lsel ? &Mt[0][lrow][8 * lhalf] : &Wt[0][lrow][8 * lhalf];
        if (lsel) {
            v0.x = tf32r(v0.x); v0.y = tf32r(v0.y); v0.z = tf32r(v0.z); v0.w = tf32r(v0.w);
            v1.x = tf32r(v1.x); v1.y = tf32r(v1.y); v1.z = tf32r(v1.z); v1.w = tf32r(v1.w);
        }
        *(float4*)dst = v0;
        *(float4*)(dst + 4) = v1;
    }
    __syncthreads();

    const int NSTEP = EDIM / 16;   // 156
    int buf = 0;
    for (int s = 0; s < NSTEP; s++) {
        float4 v0, v1;
        if (s + 1 < NSTEP) {
            v0 = *(const float4*)(lsrc + (s + 1) * 16);
            v1 = *(const float4*)(lsrc + (s + 1) * 16 + 4);
        }
#pragma unroll
        for (int kk = 0; kk < 2; kk++) {
            const int e = kk * 8 + t4;
            u32 a0 = __float_as_uint(Wt[buf][d0 + g][e]);
            u32 a1 = __float_as_uint(Wt[buf][d0 + g + 8][e]);
            u32 a2 = __float_as_uint(Wt[buf][d0 + g][e + 4]);
            u32 a3 = __float_as_uint(Wt[buf][d0 + g + 8][e + 4]);
#pragma unroll
            for (int nt = 0; nt < 4; nt++) {
                u32 b0 = __float_as_uint(Mt[buf][ph + nt * 8 + g][e]);
                u32 b1 = __float_as_uint(Mt[buf][ph + nt * 8 + g][e + 4]);
                mma_tf32(c[nt], a0, a1, a2, a3, b0, b1);
            }
        }
        __syncthreads();
        if (s + 1 < NSTEP) {
            int nb = buf ^ 1;
            float* dst = lsel ? &Mt[nb][lrow][8 * lhalf] : &Wt[nb][lrow][8 * lhalf];
            if (lsel) {
                v0.x = tf32r(v0.x); v0.y = tf32r(v0.y); v0.z = tf32r(v0.z); v0.w = tf32r(v0.w);
                v1.x = tf32r(v1.x); v1.y = tf32r(v1.y); v1.z = tf32r(v1.z); v1.w = tf32r(v1.w);
            }
            *(float4*)dst = v0;
            *(float4*)(dst + 4) = v1;
            __syncthreads();
        }
        buf ^= 1;
    }

    // epilogue: c[nt][0..1] -> row d0+g, cols 2*t4, 2*t4+1 ; c[nt][2..3] -> row d0+g+8
#pragma unroll
    for (int nt = 0; nt < 4; nt++) {
        int pcol = p1 + ph + nt * 8 + 2 * t4;
        float* f0 = &g_feat[((size_t)r * DO + d0 + g) * VV + pcol];
        float* f1 = &g_feat[((size_t)r * DO + d0 + g + 8) * VV + pcol];
        *(float2*)f0 = make_float2(c[nt][0], c[nt][1]);
        *(float2*)f1 = make_float2(c[nt][2], c[nt][3]);
    }
}

// ---------------- kernel C: ka = max over C2V pairs of feat ----------------
__global__ void kernC(float* __restrict__ out) {
    int idx = blockIdx.x * blockDim.x + threadIdx.x;   // over DO*VV
    if (idx >= DO * VV) return;
    int d = idx / VV, p = idx % VV;
#pragma unroll
    for (int col = 0; col < 6; col++) {
        int r0 = cC2V[col][0], r1 = cC2V[col][1];
        float v = fmaxf(g_feat[((size_t)r0 * DO + d) * VV + p],
                        g_feat[((size_t)r1 * DO + d) * VV + p]);
        out[(size_t)idx * 6 + col] = v;
    }
}

extern "C" void kernel_launch(void* const* d_in, const int* in_sizes, int n_in,
                              void* d_out, int out_size) {
    const int*   nbr   = (const int*)d_in[0];
    const float* verts = (const float*)d_in[1];
    const float* fm    = (const float*)d_in[2];
    const float* wdim  = (const float*)d_in[3];
    const float* W     = (const float*)d_in[4];
    const float* Wdir  = (const float*)d_in[5];
    float* out = (float*)d_out;

    prepWdr<<<(CID * NT + 255) / 256, 256>>>(Wdir);
    prepWg<<<(12 * DO * EDIM + 255) / 256, 256>>>(W);
    kernA<<<VV / 2, 192>>>(nbr, verts, fm, wdim);
    dim3 gb(VV / 64, 12);
    kernB<<<gb, 256>>>();
    kernC<<<(DO * VV + 255) / 256, 256>>>(out);
    if (out_size >= KA_ELEMS + FM_ELEMS) {
        cudaMemcpyAsync(out + KA_ELEMS, fm, (size_t)FM_ELEMS * sizeof(float),
                        cudaMemcpyDeviceToDevice, 0);
    }
}

// round 7
// speedup vs baseline: 1.9274x; 1.4585x over previous
#include <cuda_runtime.h>
#include <cstddef>

// Problem constants (fixed-shape benchmark)
#define VV   2048
#define NN   16
#define DI   32
#define DO   64
#define NH   8
#define NT   1152          // tasks = H*12*12
#define CID  192           // DI*6
#define EDIM 2496          // 32*13*6
#define MROW 29952         // 12*EDIM
#define PN   32768         // VV*16
#define KA_ELEMS (DO*VV*6)     // 786432
#define FM_ELEMS (DI*VV*6)     // 393216

typedef unsigned long long u64;
typedef unsigned int u32;

// ---------------- helpers ----------------
__device__ __forceinline__ u64 bc2(float x) {
    u64 r; asm("mov.b64 %0,{%1,%1};" : "=l"(r) : "f"(x)); return r;
}
__device__ __forceinline__ void up2(float& x, float& y, u64 v) {
    asm("mov.b64 {%0,%1},%2;" : "=f"(x), "=f"(y) : "l"(v));
}
__device__ __forceinline__ void fma2(u64& d, u64 a, u64 b) {
    asm("fma.rn.f32x2 %0,%1,%2,%0;" : "+l"(d) : "l"(a), "l"(b));
}
__device__ __forceinline__ float tf32r(float x) {
    u32 r; asm("cvt.rna.tf32.f32 %0,%1;" : "=r"(r) : "f"(x));
    return __uint_as_float(r);
}
__device__ __forceinline__ void mma_tf32(float c[4], u32 a0, u32 a1, u32 a2, u32 a3,
                                         u32 b0, u32 b1) {
    asm volatile("mma.sync.aligned.m16n8k8.row.col.f32.tf32.tf32.f32 "
                 "{%0,%1,%2,%3}, {%4,%5,%6,%7}, {%8,%9}, {%0,%1,%2,%3};"
                 : "+f"(c[0]), "+f"(c[1]), "+f"(c[2]), "+f"(c[3])
                 : "r"(a0), "r"(a1), "r"(a2), "r"(a3), "r"(b0), "r"(b1));
}

// ---------------- constant tables ----------------
__constant__ int cINV[12][6] = {
    {0,1,2,3,4,5},{0,5,4,3,2,1},{4,3,0,5,2,1},{1,2,4,3,5,0},
    {3,5,2,0,4,1},{1,4,3,5,0,2},{4,0,3,1,2,5},{1,0,2,4,3,5},
    {4,1,2,5,0,3},{3,1,4,0,2,5},{2,1,4,5,3,0},{4,5,0,3,1,2}};
__constant__ int cROLL[5][6] = {
    {0,1,2,3,4,5},{0,2,3,4,5,1},{0,3,4,5,1,2},{0,4,5,1,2,3},{0,5,1,2,3,4}};
__constant__ int cC2V[6][2] = {{0,1},{6,7},{2,11},{4,9},{5,8},{3,10}};
#define PHI 1.6180339887498949f
__constant__ float cVSU[12][3] = {
    {0.f,1.f,PHI},{0.f,1.f,-PHI},{0.f,-1.f,PHI},{0.f,-1.f,-PHI},
    {1.f,PHI,0.f},{1.f,-PHI,0.f},{-1.f,PHI,0.f},{-1.f,-PHI,0.f},
    {PHI,0.f,1.f},{PHI,0.f,-1.f},{-PHI,0.f,1.f},{-PHI,0.f,-1.f}};

// ---------------- device scratch ----------------
__device__ float g_Wdr[CID * NT];                 // [ci][task], tf32-rounded, 0.5 folded
__device__ float g_Wg[12 * DO * EDIM];            // [r][d][e] (tf32-rounded)
__device__ float g_cross[(size_t)CID * PN];       // [ci][p*16+n]  full fp32
__device__ float g_act[(size_t)NT * PN];          // [t][p*16+n]
__device__ float g_M[(size_t)VV * MROW];          // [p][r][e]
__device__ float g_feat[12 * DO * VV];            // [r][d][p]

// ---------------- symmetry expansion ----------------
__device__ __forceinline__ float w13v(const float* Wp, int k, int j) {
    if (k == 0)  return (j == 0) ? Wp[0] : Wp[1];
    if (k == 1)  return (j == 0) ? Wp[2] : Wp[3];
    if (k == 12) return (j == 0) ? Wp[4] : Wp[5];
    if (k < 7)   return Wp[6  + cROLL[k - 2][j]];
    return               Wp[12 + cROLL[k - 7][j]];
}

__global__ void prepWdr(const float* __restrict__ Wdir) {
    int idx = blockIdx.x * blockDim.x + threadIdx.x;
    if (idx >= CID * NT) return;
    int t = idx % NT, ci = idx / NT;
    int c = ci / 6, i = ci % 6;
    int h = t / 144, k = (t / 12) % 12, r = t % 12;
    const float* Wp = Wdir + (h * 32 + c) * 18;
    g_Wdr[idx] = tf32r(0.5f * w13v(Wp, k, cINV[r][i]));
}

__global__ void prepWg(const float* __restrict__ W) {
    int idx = blockIdx.x * blockDim.x + threadIdx.x;
    if (idx >= 12 * DO * EDIM) return;
    int e = idx % EDIM;
    int d = (idx / EDIM) % DO;
    int r = idx / (EDIM * DO);
    int c = e / 78, rem = e % 78, k = rem / 6, i = rem % 6;
    const float* Wp = W + (d * 32 + c) * 18;
    g_Wg[idx] = tf32r(w13v(Wp, k, cINV[r][i]));
}

// ---------------- kernel A1: cross for 2 vertices/block -> g_cross ----------------
__global__ __launch_bounds__(192) void kernA1(const int* __restrict__ nbr_idx,
                                              const float* __restrict__ verts,
                                              const float* __restrict__ fm,
                                              const float* __restrict__ wdim) {
    const int p0 = blockIdx.x * 2;
    const int tid = threadIdx.x;
    __shared__ __align__(16) float s_cross[2][CID * 16];   // [v][ci][n]
    __shared__ __align__(16) float s_wdim[33 * 32];
    __shared__ float s_de[2][96];
    __shared__ int s_nbr[2][16];

    for (int t = tid; t < 33 * 32; t += 192) s_wdim[t] = wdim[t];

    if (tid < 32) {
        int v = tid >> 4, n = tid & 15;
        int p = p0 + v;
        int nb = nbr_idx[p * NN + n];
        s_nbr[v][n] = nb;
        float px = verts[p * 3], py = verts[p * 3 + 1], pz = verts[p * 3 + 2];
        float dx = verts[nb * 3] - px;
        float dy = verts[nb * 3 + 1] - py;
        float dz = verts[nb * 3 + 2] - pz;
        float nrm = sqrtf(dx * dx + dy * dy + dz * dz);
        float inv = 1.0f / fmaxf(nrm, 1e-12f);
        dx *= inv; dy *= inv; dz *= inv;
        const float invn = rsqrtf(2.0f + PHI);
        float d0[12];
#pragma unroll
        for (int q = 0; q < 12; q++)
            d0[q] = (cVSU[q][0] * dx + cVSU[q][1] * dy + cVSU[q][2] * dz) * invn;
#pragma unroll
        for (int col = 0; col < 6; col++)
            s_de[v][n * 6 + col] = fmaxf(d0[cC2V[col][0]], d0[cC2V[col][1]]);
    }
    __syncthreads();

    {
        int v = tid / 96, t0 = tid % 96;
        int n = t0 / 6, i = t0 % 6;
        int nb = s_nbr[v][n];
        u64 acc[16];
#pragma unroll
        for (int q = 0; q < 16; q++) acc[q] = 0ull;
        for (int c = 0; c < 33; c++) {
            float x = (c < 32) ? fm[((size_t)c * VV + nb) * 6 + i] : s_de[v][n * 6 + i];
            u64 xb = bc2(x);
            const u64* wd2 = (const u64*)&s_wdim[c * 32];
#pragma unroll
            for (int q = 0; q < 16; q++) fma2(acc[q], wd2[q], xb);
        }
#pragma unroll
        for (int q = 0; q < 16; q++) {
            float o0, o1; up2(o0, o1, acc[q]);
            s_cross[v][((2 * q)     * 6 + i) * 16 + n] = o0;
            s_cross[v][((2 * q + 1) * 6 + i) * 16 + n] = o1;
        }
    }
    __syncthreads();

    // cooperative coalesced write: 6 warps x 32 rows; 32 consecutive cols (2 vertices x 16 n)
    {
        const int warp = tid >> 5, lane = tid & 31;
        const int v = lane >> 4, n = lane & 15;
        for (int rr = 0; rr < 32; rr++) {
            int ci = warp * 32 + rr;
            g_cross[(size_t)ci * PN + p0 * 16 + lane] = s_cross[v][ci * 16 + n];
        }
    }
}

// ---------------- kernel A2 (TC GEMM): act[t][pn] = sum_ci Wdr[ci][t]*cross[ci][pn] ----------------
// M=1152 (t), N=32768 (pn), K=192. Tile 128t x 128pn, k-chunk 16, double-buffered.
#define KCH 16
#define APAD 136
__global__ __launch_bounds__(256) void kernA2() {
    const int t0 = blockIdx.y * 128;
    const int c0 = blockIdx.x * 128;
    const int tid = threadIdx.x;
    __shared__ __align__(16) float As[2][KCH][APAD];
    __shared__ __align__(16) float Bs[2][KCH][APAD];

    const int lcol = tid & 127, kh = tid >> 7;   // loader: 8 k-rows each
    const int lane = tid & 31, warp = tid >> 5;
    const int g = lane >> 2, t4 = lane & 3;
    const int wt = (warp & 3) * 32;              // warp t-offset
    const int wp = (warp >> 2) * 64;             // warp pn-offset

    float acc[2][8][4];
#pragma unroll
    for (int mt = 0; mt < 2; mt++)
#pragma unroll
        for (int nt = 0; nt < 8; nt++)
#pragma unroll
            for (int q = 0; q < 4; q++) acc[mt][nt][q] = 0.f;

    // prologue: chunk 0
#pragma unroll
    for (int j = 0; j < 8; j++) {
        int k = kh * 8 + j;
        As[0][k][lcol] = g_Wdr[(size_t)k * NT + t0 + lcol];
        Bs[0][k][lcol] = tf32r(g_cross[(size_t)k * PN + c0 + lcol]);
    }
    __syncthreads();

    const int NCH = CID / KCH;   // 12
    int buf = 0;
    for (int ch = 0; ch < NCH; ch++) {
        float pa[8], pb[8];
        if (ch + 1 < NCH) {
            int k0 = (ch + 1) * KCH;
#pragma unroll
            for (int j = 0; j < 8; j++) {
                int k = kh * 8 + j;
                pa[j] = g_Wdr[(size_t)(k0 + k) * NT + t0 + lcol];
                pb[j] = g_cross[(size_t)(k0 + k) * PN + c0 + lcol];
            }
        }
#pragma unroll
        for (int e = 0; e < 2; e++) {
            const int ks = e * 8;
#pragma unroll
            for (int mt = 0; mt < 2; mt++) {
                int row = wt + mt * 16 + g;
                u32 a0 = __float_as_uint(As[buf][ks + t4][row]);
                u32 a1 = __float_as_uint(As[buf][ks + t4][row + 8]);
                u32 a2 = __float_as_uint(As[buf][ks + t4 + 4][row]);
                u32 a3 = __float_as_uint(As[buf][ks + t4 + 4][row + 8]);
#pragma unroll
                for (int nt = 0; nt < 8; nt++) {
                    int col = wp + nt * 8 + g;
                    u32 b0 = __float_as_uint(Bs[buf][ks + t4][col]);
                    u32 b1 = __float_as_uint(Bs[buf][ks + t4 + 4][col]);
                    mma_tf32(acc[mt][nt], a0, a1, a2, a3, b0, b1);
                }
            }
        }
        __syncthreads();
        if (ch + 1 < NCH) {
            int nb = buf ^ 1;
#pragma unroll
            for (int j = 0; j < 8; j++) {
                int k = kh * 8 + j;
                As[nb][k][lcol] = pa[j];
                Bs[nb][k][lcol] = tf32r(pb[j]);
            }
            __syncthreads();
        }
        buf ^= 1;
    }

    // epilogue
#pragma unroll
    for (int mt = 0; mt < 2; mt++) {
        int row = t0 + wt + mt * 16 + g;
#pragma unroll
        for (int nt = 0; nt < 8; nt++) {
            int col = c0 + wp + nt * 8 + 2 * t4;
            *(float2*)&g_act[(size_t)row * PN + col] = make_float2(acc[mt][nt][0], acc[mt][nt][1]);
            *(float2*)&g_act[(size_t)(row + 8) * PN + col] = make_float2(acc[mt][nt][2], acc[mt][nt][3]);
        }
    }
}

// ---------------- kernel A3: per-vertex softmax + nfm -> g_M (plus center slice) ----------------
__global__ __launch_bounds__(384) void kernA3(const float* __restrict__ fm) {
    const int p = blockIdx.x;
    const int tid = threadIdx.x;
    __shared__ float s_a[384][17];            // odd stride: conflict-free row reads
    __shared__ __align__(16) float s_cv[CID * 16];

    // load cross columns for this vertex (full fp32)
#pragma unroll
    for (int q = 0; q < 2; q++) {
        int e4 = tid + q * 384;                 // 768 float4s
        int e = e4 * 4;
        int ci = e >> 4, n = e & 15;
        *(float4*)&s_cv[e] = *(const float4*)&g_cross[(size_t)ci * PN + p * 16 + n];
    }

    // center slice k=12 of M
    if (tid < 192) {
        int c = tid / 6, i = tid % 6;
        float val = fm[((size_t)c * VV + p) * 6 + i];
        size_t base = (size_t)p * MROW + (size_t)(c * 13 + 12) * 6 + i;
#pragma unroll
        for (int r = 0; r < 12; r++) g_M[base + (size_t)r * EDIM] = val;
    }

    const int j = tid & 1, rowh = tid >> 1;
    for (int chunk = 0; chunk < 3; chunk++) {
        const int tb = chunk * 384;
        __syncthreads();
#pragma unroll
        for (int pass = 0; pass < 2; pass++) {
            int tl = rowh + pass * 192;
            const float* src = &g_act[(size_t)(tb + tl) * PN + p * 16 + j * 8];
            float4 v0 = *(const float4*)src;
            float4 v1 = *(const float4*)(src + 4);
            float* dst = &s_a[tl][j * 8];      // 68B row stride -> scalar stores only
            dst[0] = v0.x; dst[1] = v0.y; dst[2] = v0.z; dst[3] = v0.w;
            dst[4] = v1.x; dst[5] = v1.y; dst[6] = v1.z; dst[7] = v1.w;
        }
        __syncthreads();

        const int t = tb + tid;
        const int h = t / 144, k = (t / 12) % 12, r = t % 12;
        float a[16];
#pragma unroll
        for (int n = 0; n < 16; n++) a[n] = s_a[tid][n];
        float m = a[0];
#pragma unroll
        for (int n = 1; n < 16; n++) m = fmaxf(m, a[n]);
        float s = 0.f;
#pragma unroll
        for (int n = 0; n < 16; n++) { a[n] = __expf(a[n] - m); s += a[n]; }
        float invs = 1.0f / s;
#pragma unroll
        for (int n = 0; n < 16; n++) a[n] *= invs;

        size_t base = (size_t)p * MROW + (size_t)r * EDIM;
#pragma unroll
        for (int cc = 0; cc < 4; cc++) {
            int c = h * 4 + cc;
            float mv[6];
#pragma unroll
            for (int i = 0; i < 6; i++) {
                const float* cp = &s_cv[(c * 6 + i) * 16];
                float acc = 0.f;
#pragma unroll
                for (int n = 0; n < 16; n++) acc += a[n] * cp[n];
                mv[i] = acc;
            }
            float2* dst2 = (float2*)&g_M[base + (size_t)(c * 13 + k) * 6];
            dst2[0] = make_float2(mv[0], mv[1]);
            dst2[1] = make_float2(mv[2], mv[3]);
            dst2[2] = make_float2(mv[4], mv[5]);
        }
    }
}

// ---------------- kernel B (tensor cores): feat[r](64x2048) = Wg[r](64x2496) @ M_r(2496x2048) ----------------
#define BPAD 20
__global__ __launch_bounds__(256) void kernB() {
    const int r  = blockIdx.y;
    const int p1 = blockIdx.x * 64;
    const int tid = threadIdx.x;
    __shared__ __align__(16) float Wt[2][64][BPAD];
    __shared__ __align__(16) float Mt[2][64][BPAD];

    const int lsel  = tid >> 7;           // 0 = W, 1 = M
    const int lrow  = (tid >> 1) & 63;
    const int lhalf = tid & 1;
    const float* lsrc = lsel
        ? (g_M + ((size_t)(p1 + lrow)) * MROW + (size_t)r * EDIM + 8 * lhalf)
        : (g_Wg + ((size_t)r * DO + lrow) * EDIM + 8 * lhalf);

    const int lane = tid & 31, warp = tid >> 5;
    const int g = lane >> 2, t4 = lane & 3;
    const int d0 = (warp & 3) * 16;
    const int ph = (warp >> 2) * 32;

    float c[4][4];
#pragma unroll
    for (int nt = 0; nt < 4; nt++)
#pragma unroll
        for (int q = 0; q < 4; q++) c[nt][q] = 0.f;

    {
        float4 v0 = *(const float4*)(lsrc);
        float4 v1 = *(const float4*)(lsrc + 4);
        float* dst = lsel ? &Mt[0][lrow][8 * lhalf] : &Wt[0][lrow][8 * lhalf];
        if (lsel) {
            v0.x = tf32r(v0.x); v0.y = tf32r(v0.y); v0.z = tf32r(v0.z); v0.w = tf32r(v0.w);
            v1.x = tf32r(v1.x); v1.y = tf32r(v1.y); v1.z = tf32r(v1.z); v1.w = tf32r(v1.w);
        }
        *(float4*)dst = v0;
        *(float4*)(dst + 4) = v1;
    }
    __syncthreads();

    const int NSTEP = EDIM / 16;   // 156
    int buf = 0;
    for (int s = 0; s < NSTEP; s++) {
        float4 v0, v1;
        if (s + 1 < NSTEP) {
            v0 = *(const float4*)(lsrc + (s + 1) * 16);
            v1 = *(const float4*)(lsrc + (s + 1) * 16 + 4);
        }
#pragma unroll
        for (int kk = 0; kk < 2; kk++) {
            const int e = kk * 8 + t4;
            u32 a0 = __float_as_uint(Wt[buf][d0 + g][e]);
            u32 a1 = __float_as_uint(Wt[buf][d0 + g + 8][e]);
            u32 a2 = __float_as_uint(Wt[buf][d0 + g][e + 4]);
            u32 a3 = __float_as_uint(Wt[buf][d0 + g + 8][e + 4]);
#pragma unroll
            for (int nt = 0; nt < 4; nt++) {
                u32 b0 = __float_as_uint(Mt[buf][ph + nt * 8 + g][e]);
                u32 b1 = __float_as_uint(Mt[buf][ph + nt * 8 + g][e + 4]);
                mma_tf32(c[nt], a0, a1, a2, a3, b0, b1);
            }
        }
        __syncthreads();
        if (s + 1 < NSTEP) {
            int nb = buf ^ 1;
            float* dst = lsel ? &Mt[nb][lrow][8 * lhalf] : &Wt[nb][lrow][8 * lhalf];
            if (lsel) {
                v0.x = tf32r(v0.x); v0.y = tf32r(v0.y); v0.z = tf32r(v0.z); v0.w = tf32r(v0.w);
                v1.x = tf32r(v1.x); v1.y = tf32r(v1.y); v1.z = tf32r(v1.z); v1.w = tf32r(v1.w);
            }
            *(float4*)dst = v0;
            *(float4*)(dst + 4) = v1;
            __syncthreads();
        }
        buf ^= 1;
    }

#pragma unroll
    for (int nt = 0; nt < 4; nt++) {
        int pcol = p1 + ph + nt * 8 + 2 * t4;
        float* f0 = &g_feat[((size_t)r * DO + d0 + g) * VV + pcol];
        float* f1 = &g_feat[((size_t)r * DO + d0 + g + 8) * VV + pcol];
        *(float2*)f0 = make_float2(c[nt][0], c[nt][1]);
        *(float2*)f1 = make_float2(c[nt][2], c[nt][3]);
    }
}

// ---------------- kernel C: ka = max over C2V pairs of feat ----------------
__global__ void kernC(float* __restrict__ out) {
    int idx = blockIdx.x * blockDim.x + threadIdx.x;   // over DO*VV
    if (idx >= DO * VV) return;
    int d = idx / VV, p = idx % VV;
#pragma unroll
    for (int col = 0; col < 6; col++) {
        int r0 = cC2V[col][0], r1 = cC2V[col][1];
        float v = fmaxf(g_feat[((size_t)r0 * DO + d) * VV + p],
                        g_feat[((size_t)r1 * DO + d) * VV + p]);
        out[(size_t)idx * 6 + col] = v;
    }
}

extern "C" void kernel_launch(void* const* d_in, const int* in_sizes, int n_in,
                              void* d_out, int out_size) {
    const int*   nbr   = (const int*)d_in[0];
    const float* verts = (const float*)d_in[1];
    const float* fm    = (const float*)d_in[2];
    const float* wdim  = (const float*)d_in[3];
    const float* W     = (const float*)d_in[4];
    const float* Wdir  = (const float*)d_in[5];
    float* out = (float*)d_out;

    prepWdr<<<(CID * NT + 255) / 256, 256>>>(Wdir);
    prepWg<<<(12 * DO * EDIM + 255) / 256, 256>>>(W);
    kernA1<<<VV / 2, 192>>>(nbr, verts, fm, wdim);
    {
        dim3 ga(PN / 128, NT / 128);           // 256 x 9
        kernA2<<<ga, 256>>>();
    }
    kernA3<<<VV, 384>>>(fm);
    {
        dim3 gb(VV / 64, 12);
        kernB<<<gb, 256>>>();
    }
    kernC<<<(DO * VV + 255) / 256, 256>>>(out);
    if (out_size >= KA_ELEMS + FM_ELEMS) {
        cudaMemcpyAsync(out + KA_ELEMS, fm, (size_t)FM_ELEMS * sizeof(float),
                        cudaMemcpyDeviceToDevice, 0);
    }
}

// round 8
// speedup vs baseline: 2.0716x; 1.0748x over previous
#include <cuda_runtime.h>
#include <cstddef>

// Problem constants (fixed-shape benchmark)
#define VV   2048
#define NN   16
#define DI   32
#define DO   64
#define NH   8
#define NT   1152          // tasks = H*12*12
#define CID  192           // DI*6
#define EDIM 2496          // 32*13*6
#define MROW 29952         // 12*EDIM
#define PN   32768         // VV*16
#define KA_ELEMS (DO*VV*6)     // 786432
#define FM_ELEMS (DI*VV*6)     // 393216

typedef unsigned long long u64;
typedef unsigned int u32;

// ---------------- helpers ----------------
__device__ __forceinline__ u64 bc2(float x) {
    u64 r; asm("mov.b64 %0,{%1,%1};" : "=l"(r) : "f"(x)); return r;
}
__device__ __forceinline__ void up2(float& x, float& y, u64 v) {
    asm("mov.b64 {%0,%1},%2;" : "=f"(x), "=f"(y) : "l"(v));
}
__device__ __forceinline__ void fma2(u64& d, u64 a, u64 b) {
    asm("fma.rn.f32x2 %0,%1,%2,%0;" : "+l"(d) : "l"(a), "l"(b));
}
__device__ __forceinline__ float tf32r(float x) {
    u32 r; asm("cvt.rna.tf32.f32 %0,%1;" : "=r"(r) : "f"(x));
    return __uint_as_float(r);
}
__device__ __forceinline__ void mma_tf32(float c[4], u32 a0, u32 a1, u32 a2, u32 a3,
                                         u32 b0, u32 b1) {
    asm volatile("mma.sync.aligned.m16n8k8.row.col.f32.tf32.tf32.f32 "
                 "{%0,%1,%2,%3}, {%4,%5,%6,%7}, {%8,%9}, {%0,%1,%2,%3};"
                 : "+f"(c[0]), "+f"(c[1]), "+f"(c[2]), "+f"(c[3])
                 : "r"(a0), "r"(a1), "r"(a2), "r"(a3), "r"(b0), "r"(b1));
}

// ---------------- constant tables ----------------
__constant__ int cINV[12][6] = {
    {0,1,2,3,4,5},{0,5,4,3,2,1},{4,3,0,5,2,1},{1,2,4,3,5,0},
    {3,5,2,0,4,1},{1,4,3,5,0,2},{4,0,3,1,2,5},{1,0,2,4,3,5},
    {4,1,2,5,0,3},{3,1,4,0,2,5},{2,1,4,5,3,0},{4,5,0,3,1,2}};
__constant__ int cROLL[5][6] = {
    {0,1,2,3,4,5},{0,2,3,4,5,1},{0,3,4,5,1,2},{0,4,5,1,2,3},{0,5,1,2,3,4}};
__constant__ int cC2V[6][2] = {{0,1},{6,7},{2,11},{4,9},{5,8},{3,10}};
#define PHI 1.6180339887498949f
__constant__ float cVSU[12][3] = {
    {0.f,1.f,PHI},{0.f,1.f,-PHI},{0.f,-1.f,PHI},{0.f,-1.f,-PHI},
    {1.f,PHI,0.f},{1.f,-PHI,0.f},{-1.f,PHI,0.f},{-1.f,-PHI,0.f},
    {PHI,0.f,1.f},{PHI,0.f,-1.f},{-PHI,0.f,1.f},{-PHI,0.f,-1.f}};

// ---------------- device scratch ----------------
__device__ float g_Wdr[CID * NT];                 // [ci][task], tf32-rounded, 0.5 folded
__device__ float g_Wg[12 * DO * EDIM];            // [r][d][e] (tf32-rounded)
__device__ float g_cross[(size_t)CID * PN];       // [ci][p*16+n]  full fp32
__device__ float g_act[(size_t)NT * PN];          // [t][p*16+n]
__device__ float g_M[(size_t)VV * MROW];          // [p][r][e]
__device__ float g_feat[12 * DO * VV];            // [r][d][p]

// ---------------- symmetry expansion ----------------
__device__ __forceinline__ float w13v(const float* Wp, int k, int j) {
    if (k == 0)  return (j == 0) ? Wp[0] : Wp[1];
    if (k == 1)  return (j == 0) ? Wp[2] : Wp[3];
    if (k == 12) return (j == 0) ? Wp[4] : Wp[5];
    if (k < 7)   return Wp[6  + cROLL[k - 2][j]];
    return               Wp[12 + cROLL[k - 7][j]];
}

__global__ void prepWdr(const float* __restrict__ Wdir) {
    int idx = blockIdx.x * blockDim.x + threadIdx.x;
    if (idx >= CID * NT) return;
    int t = idx % NT, ci = idx / NT;
    int c = ci / 6, i = ci % 6;
    int h = t / 144, k = (t / 12) % 12, r = t % 12;
    const float* Wp = Wdir + (h * 32 + c) * 18;
    g_Wdr[idx] = tf32r(0.5f * w13v(Wp, k, cINV[r][i]));
}

__global__ void prepWg(const float* __restrict__ W) {
    int idx = blockIdx.x * blockDim.x + threadIdx.x;
    if (idx >= 12 * DO * EDIM) return;
    int e = idx % EDIM;
    int d = (idx / EDIM) % DO;
    int r = idx / (EDIM * DO);
    int c = e / 78, rem = e % 78, k = rem / 6, i = rem % 6;
    const float* Wp = W + (d * 32 + c) * 18;
    g_Wg[idx] = tf32r(w13v(Wp, k, cINV[r][i]));
}

// ---------------- kernel A1: cross for 2 vertices/block -> g_cross ----------------
__global__ __launch_bounds__(192) void kernA1(const int* __restrict__ nbr_idx,
                                              const float* __restrict__ verts,
                                              const float* __restrict__ fm,
                                              const float* __restrict__ wdim) {
    const int p0 = blockIdx.x * 2;
    const int tid = threadIdx.x;
    __shared__ __align__(16) float s_cross[2][CID * 16];   // [v][ci][n]
    __shared__ __align__(16) float s_wdim[33 * 32];
    __shared__ float s_de[2][96];
    __shared__ int s_nbr[2][16];

    for (int t = tid; t < 33 * 32; t += 192) s_wdim[t] = wdim[t];

    if (tid < 32) {
        int v = tid >> 4, n = tid & 15;
        int p = p0 + v;
        int nb = nbr_idx[p * NN + n];
        s_nbr[v][n] = nb;
        float px = verts[p * 3], py = verts[p * 3 + 1], pz = verts[p * 3 + 2];
        float dx = verts[nb * 3] - px;
        float dy = verts[nb * 3 + 1] - py;
        float dz = verts[nb * 3 + 2] - pz;
        float nrm = sqrtf(dx * dx + dy * dy + dz * dz);
        float inv = 1.0f / fmaxf(nrm, 1e-12f);
        dx *= inv; dy *= inv; dz *= inv;
        const float invn = rsqrtf(2.0f + PHI);
        float d0[12];
#pragma unroll
        for (int q = 0; q < 12; q++)
            d0[q] = (cVSU[q][0] * dx + cVSU[q][1] * dy + cVSU[q][2] * dz) * invn;
#pragma unroll
        for (int col = 0; col < 6; col++)
            s_de[v][n * 6 + col] = fmaxf(d0[cC2V[col][0]], d0[cC2V[col][1]]);
    }
    __syncthreads();

    {
        int v = tid / 96, t0 = tid % 96;
        int n = t0 / 6, i = t0 % 6;
        int nb = s_nbr[v][n];
        u64 acc[16];
#pragma unroll
        for (int q = 0; q < 16; q++) acc[q] = 0ull;
        for (int c = 0; c < 33; c++) {
            float x = (c < 32) ? fm[((size_t)c * VV + nb) * 6 + i] : s_de[v][n * 6 + i];
            u64 xb = bc2(x);
            const u64* wd2 = (const u64*)&s_wdim[c * 32];
#pragma unroll
            for (int q = 0; q < 16; q++) fma2(acc[q], wd2[q], xb);
        }
#pragma unroll
        for (int q = 0; q < 16; q++) {
            float o0, o1; up2(o0, o1, acc[q]);
            s_cross[v][((2 * q)     * 6 + i) * 16 + n] = o0;
            s_cross[v][((2 * q + 1) * 6 + i) * 16 + n] = o1;
        }
    }
    __syncthreads();

    // cooperative coalesced write: 6 warps x 32 rows; 32 consecutive cols (2 vertices x 16 n)
    {
        const int warp = tid >> 5, lane = tid & 31;
        const int v = lane >> 4, n = lane & 15;
        for (int rr = 0; rr < 32; rr++) {
            int ci = warp * 32 + rr;
            g_cross[(size_t)ci * PN + p0 * 16 + lane] = s_cross[v][ci * 16 + n];
        }
    }
}

// ---------------- kernel A2 (TC GEMM): act[t][pn] = sum_ci Wdr[ci][t]*cross[ci][pn] ----------------
// M=1152 (t), N=32768 (pn), K=192. Tile 128t x 128pn, k-chunk 16, double-buffered.
#define KCH 16
#define APAD 136
__global__ __launch_bounds__(256) void kernA2() {
    const int t0 = blockIdx.y * 128;
    const int c0 = blockIdx.x * 128;
    const int tid = threadIdx.x;
    __shared__ __align__(16) float As[2][KCH][APAD];
    __shared__ __align__(16) float Bs[2][KCH][APAD];

    const int lcol = tid & 127, kh = tid >> 7;   // loader: 8 k-rows each
    const int lane = tid & 31, warp = tid >> 5;
    const int g = lane >> 2, t4 = lane & 3;
    const int wt = (warp & 3) * 32;              // warp t-offset
    const int wp = (warp >> 2) * 64;             // warp pn-offset

    float acc[2][8][4];
#pragma unroll
    for (int mt = 0; mt < 2; mt++)
#pragma unroll
        for (int nt = 0; nt < 8; nt++)
#pragma unroll
            for (int q = 0; q < 4; q++) acc[mt][nt][q] = 0.f;

    // prologue: chunk 0
#pragma unroll
    for (int j = 0; j < 8; j++) {
        int k = kh * 8 + j;
        As[0][k][lcol] = g_Wdr[(size_t)k * NT + t0 + lcol];
        Bs[0][k][lcol] = tf32r(g_cross[(size_t)k * PN + c0 + lcol]);
    }
    __syncthreads();

    const int NCH = CID / KCH;   // 12
    int buf = 0;
    for (int ch = 0; ch < NCH; ch++) {
        float pa[8], pb[8];
        if (ch + 1 < NCH) {
            int k0 = (ch + 1) * KCH;
#pragma unroll
            for (int j = 0; j < 8; j++) {
                int k = kh * 8 + j;
                pa[j] = g_Wdr[(size_t)(k0 + k) * NT + t0 + lcol];
                pb[j] = g_cross[(size_t)(k0 + k) * PN + c0 + lcol];
            }
        }
#pragma unroll
        for (int e = 0; e < 2; e++) {
            const int ks = e * 8;
#pragma unroll
            for (int mt = 0; mt < 2; mt++) {
                int row = wt + mt * 16 + g;
                u32 a0 = __float_as_uint(As[buf][ks + t4][row]);
                u32 a1 = __float_as_uint(As[buf][ks + t4][row + 8]);
                u32 a2 = __float_as_uint(As[buf][ks + t4 + 4][row]);
                u32 a3 = __float_as_uint(As[buf][ks + t4 + 4][row + 8]);
#pragma unroll
                for (int nt = 0; nt < 8; nt++) {
                    int col = wp + nt * 8 + g;
                    u32 b0 = __float_as_uint(Bs[buf][ks + t4][col]);
                    u32 b1 = __float_as_uint(Bs[buf][ks + t4 + 4][col]);
                    mma_tf32(acc[mt][nt], a0, a1, a2, a3, b0, b1);
                }
            }
        }
        __syncthreads();
        if (ch + 1 < NCH) {
            int nb = buf ^ 1;
#pragma unroll
            for (int j = 0; j < 8; j++) {
                int k = kh * 8 + j;
                As[nb][k][lcol] = pa[j];
                Bs[nb][k][lcol] = tf32r(pb[j]);
            }
            __syncthreads();
        }
        buf ^= 1;
    }

    // epilogue
#pragma unroll
    for (int mt = 0; mt < 2; mt++) {
        int row = t0 + wt + mt * 16 + g;
#pragma unroll
        for (int nt = 0; nt < 8; nt++) {
            int col = c0 + wp + nt * 8 + 2 * t4;
            *(float2*)&g_act[(size_t)row * PN + col] = make_float2(acc[mt][nt][0], acc[mt][nt][1]);
            *(float2*)&g_act[(size_t)(row + 8) * PN + col] = make_float2(acc[mt][nt][2], acc[mt][nt][3]);
        }
    }
}

// ---------------- kernel A3: per-vertex softmax + nfm -> g_M (plus center slice) ----------------
__global__ __launch_bounds__(384) void kernA3(const float* __restrict__ fm) {
    const int p = blockIdx.x;
    const int tid = threadIdx.x;
    __shared__ float s_a[384][17];            // odd stride: conflict-free row reads
    __shared__ __align__(16) float s_cv[CID * 16];

    // load cross columns for this vertex (full fp32)
#pragma unroll
    for (int q = 0; q < 2; q++) {
        int e4 = tid + q * 384;                 // 768 float4s
        int e = e4 * 4;
        int ci = e >> 4, n = e & 15;
        *(float4*)&s_cv[e] = *(const float4*)&g_cross[(size_t)ci * PN + p * 16 + n];
    }

    // center slice k=12 of M
    if (tid < 192) {
        int c = tid / 6, i = tid % 6;
        float val = fm[((size_t)c * VV + p) * 6 + i];
        size_t base = (size_t)p * MROW + (size_t)(c * 13 + 12) * 6 + i;
#pragma unroll
        for (int r = 0; r < 12; r++) g_M[base + (size_t)r * EDIM] = val;
    }

    const int j = tid & 1, rowh = tid >> 1;
    for (int chunk = 0; chunk < 3; chunk++) {
        const int tb = chunk * 384;
        __syncthreads();
#pragma unroll
        for (int pass = 0; pass < 2; pass++) {
            int tl = rowh + pass * 192;
            const float* src = &g_act[(size_t)(tb + tl) * PN + p * 16 + j * 8];
            float4 v0 = *(const float4*)src;
            float4 v1 = *(const float4*)(src + 4);
            float* dst = &s_a[tl][j * 8];      // 68B row stride -> scalar stores only
            dst[0] = v0.x; dst[1] = v0.y; dst[2] = v0.z; dst[3] = v0.w;
            dst[4] = v1.x; dst[5] = v1.y; dst[6] = v1.z; dst[7] = v1.w;
        }
        __syncthreads();

        const int t = tb + tid;
        const int h = t / 144, k = (t / 12) % 12, r = t % 12;
        float a[16];
#pragma unroll
        for (int n = 0; n < 16; n++) a[n] = s_a[tid][n];
        float m = a[0];
#pragma unroll
        for (int n = 1; n < 16; n++) m = fmaxf(m, a[n]);
        float s = 0.f;
#pragma unroll
        for (int n = 0; n < 16; n++) { a[n] = __expf(a[n] - m); s += a[n]; }
        float invs = 1.0f / s;
#pragma unroll
        for (int n = 0; n < 16; n++) a[n] *= invs;

        size_t base = (size_t)p * MROW + (size_t)r * EDIM;
#pragma unroll
        for (int cc = 0; cc < 4; cc++) {
            int c = h * 4 + cc;
            float mv[6];
#pragma unroll
            for (int i = 0; i < 6; i++) {
                const float* cp = &s_cv[(c * 6 + i) * 16];
                float acc = 0.f;
#pragma unroll
                for (int n = 0; n < 16; n++) acc += a[n] * cp[n];
                mv[i] = acc;
            }
            float2* dst2 = (float2*)&g_M[base + (size_t)(c * 13 + k) * 6];
            dst2[0] = make_float2(mv[0], mv[1]);
            dst2[1] = make_float2(mv[2], mv[3]);
            dst2[2] = make_float2(mv[4], mv[5]);
        }
    }
}

// ---------------- kernel B (tensor cores): feat[r](64x2048) = Wg[r](64x2496) @ M_r(2496x2048) ----------------
// 128 threads / 4 warps; block tile 64d x 64p; warp tile 32d x 32p (2 m-tiles x 4 n-tiles).
#define BPAD 20
__global__ __launch_bounds__(128) void kernB() {
    const int r  = blockIdx.y;
    const int p1 = blockIdx.x * 64;
    const int tid = threadIdx.x;
    __shared__ __align__(16) float Wt[2][64][BPAD];
    __shared__ __align__(16) float Mt[2][64][BPAD];

    const int lane = tid & 31, warp = tid >> 5;
    const int g = lane >> 2, t4 = lane & 3;
    const int d0w = (warp & 1) * 32;
    const int p0w = (warp >> 1) * 32;

    // loader: 2 tasks per thread for each of W and M.
    // task = tid + 128*j : row = task>>2 (0..63), e4 = task&3 (0..3)
    const int lrow0 = tid >> 2, le0 = tid & 3;
    const int lrow1 = (tid + 128) >> 2, le1 = (tid + 128) & 3;
    const float* wb0 = g_Wg + ((size_t)r * DO + lrow0) * EDIM + le0 * 4;
    const float* wb1 = g_Wg + ((size_t)r * DO + lrow1) * EDIM + le1 * 4;
    const float* mb0 = g_M + (size_t)(p1 + lrow0) * MROW + (size_t)r * EDIM + le0 * 4;
    const float* mb1 = g_M + (size_t)(p1 + lrow1) * MROW + (size_t)r * EDIM + le1 * 4;

    float acc[2][4][4];
#pragma unroll
    for (int mt = 0; mt < 2; mt++)
#pragma unroll
        for (int nt = 0; nt < 4; nt++)
#pragma unroll
            for (int q = 0; q < 4; q++) acc[mt][nt][q] = 0.f;

    // prologue stage 0
    {
        float4 w0 = *(const float4*)wb0;
        float4 w1 = *(const float4*)wb1;
        float4 m0 = *(const float4*)mb0;
        float4 m1 = *(const float4*)mb1;
        m0.x = tf32r(m0.x); m0.y = tf32r(m0.y); m0.z = tf32r(m0.z); m0.w = tf32r(m0.w);
        m1.x = tf32r(m1.x); m1.y = tf32r(m1.y); m1.z = tf32r(m1.z); m1.w = tf32r(m1.w);
        *(float4*)&Wt[0][lrow0][le0 * 4] = w0;
        *(float4*)&Wt[0][lrow1][le1 * 4] = w1;
        *(float4*)&Mt[0][lrow0][le0 * 4] = m0;
        *(float4*)&Mt[0][lrow1][le1 * 4] = m1;
    }
    __syncthreads();

    const int NSTEP = EDIM / 16;   // 156
    int buf = 0;
    for (int s = 0; s < NSTEP; s++) {
        float4 w0, w1, m0, m1;
        if (s + 1 < NSTEP) {
            int eo = (s + 1) * 16;
            w0 = *(const float4*)(wb0 + eo);
            w1 = *(const float4*)(wb1 + eo);
            m0 = *(const float4*)(mb0 + eo);
            m1 = *(const float4*)(mb1 + eo);
        }
#pragma unroll
        for (int kk = 0; kk < 2; kk++) {
            const int e = kk * 8 + t4;
#pragma unroll
            for (int mt = 0; mt < 2; mt++) {
                const int ar = d0w + mt * 16 + g;
                u32 a0 = __float_as_uint(Wt[buf][ar][e]);
                u32 a1 = __float_as_uint(Wt[buf][ar + 8][e]);
                u32 a2 = __float_as_uint(Wt[buf][ar][e + 4]);
                u32 a3 = __float_as_uint(Wt[buf][ar + 8][e + 4]);
#pragma unroll
                for (int nt = 0; nt < 4; nt++) {
                    const int br = p0w + nt * 8 + g;
                    u32 b0 = __float_as_uint(Mt[buf][br][e]);
                    u32 b1 = __float_as_uint(Mt[buf][br][e + 4]);
                    mma_tf32(acc[mt][nt], a0, a1, a2, a3, b0, b1);
                }
            }
        }
        __syncthreads();
        if (s + 1 < NSTEP) {
            int nb = buf ^ 1;
            m0.x = tf32r(m0.x); m0.y = tf32r(m0.y); m0.z = tf32r(m0.z); m0.w = tf32r(m0.w);
            m1.x = tf32r(m1.x); m1.y = tf32r(m1.y); m1.z = tf32r(m1.z); m1.w = tf32r(m1.w);
            *(float4*)&Wt[nb][lrow0][le0 * 4] = w0;
            *(float4*)&Wt[nb][lrow1][le1 * 4] = w1;
            *(float4*)&Mt[nb][lrow0][le0 * 4] = m0;
            *(float4*)&Mt[nb][lrow1][le1 * 4] = m1;
            __syncthreads();
        }
        buf ^= 1;
    }

    // epilogue
#pragma unroll
    for (int mt = 0; mt < 2; mt++) {
#pragma unroll
        for (int nt = 0; nt < 4; nt++) {
            int pcol = p1 + p0w + nt * 8 + 2 * t4;
            int drow = d0w + mt * 16 + g;
            float* f0 = &g_feat[((size_t)r * DO + drow) * VV + pcol];
            float* f1 = &g_feat[((size_t)r * DO + drow + 8) * VV + pcol];
            *(float2*)f0 = make_float2(acc[mt][nt][0], acc[mt][nt][1]);
            *(float2*)f1 = make_float2(acc[mt][nt][2], acc[mt][nt][3]);
        }
    }
}

// ---------------- kernel C: ka = max over C2V pairs of feat ----------------
__global__ void kernC(float* __restrict__ out) {
    int idx = blockIdx.x * blockDim.x + threadIdx.x;   // over DO*VV
    if (idx >= DO * VV) return;
    int d = idx / VV, p = idx % VV;
#pragma unroll
    for (int col = 0; col < 6; col++) {
        int r0 = cC2V[col][0], r1 = cC2V[col][1];
        float v = fmaxf(g_feat[((size_t)r0 * DO + d) * VV + p],
                        g_feat[((size_t)r1 * DO + d) * VV + p]);
        out[(size_t)idx * 6 + col] = v;
    }
}

extern "C" void kernel_launch(void* const* d_in, const int* in_sizes, int n_in,
                              void* d_out, int out_size) {
    const int*   nbr   = (const int*)d_in[0];
    const float* verts = (const float*)d_in[1];
    const float* fm    = (const float*)d_in[2];
    const float* wdim  = (const float*)d_in[3];
    const float* W     = (const float*)d_in[4];
    const float* Wdir  = (const float*)d_in[5];
    float* out = (float*)d_out;

    prepWdr<<<(CID * NT + 255) / 256, 256>>>(Wdir);
    prepWg<<<(12 * DO * EDIM + 255) / 256, 256>>>(W);
    kernA1<<<VV / 2, 192>>>(nbr, verts, fm, wdim);
    {
        dim3 ga(PN / 128, NT / 128);           // 256 x 9
        kernA2<<<ga, 256>>>();
    }
    kernA3<<<VV, 384>>>(fm);
    {
        dim3 gb(VV / 64, 12);
        kernB<<<gb, 128>>>();
    }
    kernC<<<(DO * VV + 255) / 256, 256>>>(out);
    if (out_size >= KA_ELEMS + FM_ELEMS) {
        cudaMemcpyAsync(out + KA_ELEMS, fm, (size_t)FM_ELEMS * sizeof(float),
                        cudaMemcpyDeviceToDevice, 0);
    }
}